// round 4
// baseline (speedup 1.0000x reference)
#include <cuda_runtime.h>
#include <mma.h>

using namespace nvcuda;
namespace wm = nvcuda::wmma;

// ---------------------------------------------------------------------------
// Scratch (device globals)
// ---------------------------------------------------------------------------
__device__ float g_q [2u * 2048u * 1024u];
__device__ float g_k [2u * 2048u * 1024u];
__device__ float g_v [2u * 2048u * 1024u];
__device__ float g_yt[2u * 2048u * 1024u];

// ---------------------------------------------------------------------------
// TF32 WMMA GEMM, double-buffered: C = A[M,K] @ B[K,N] + bias[N]
// BM=128, BN=128, BK=32, 256 threads (8 warps 4x2), warp tile 32x64.
// Next K-tile is prefetched into registers while mma runs on current tile.
// Output routed into one of 3 buffers of width 1024 (QKV split).
// ---------------------------------------------------------------------------
#define G_ALD 40
#define G_BLD 136

__global__ __launch_bounds__(256) void gemm_tf32_kernel(
    const float* __restrict__ A, const float* __restrict__ B,
    const float* __restrict__ bias,
    float* __restrict__ out0, float* __restrict__ out1, float* __restrict__ out2,
    int M, int N, int K)
{
    extern __shared__ float gsm[];
    float* As[2] = { gsm,               gsm + 128 * G_ALD };
    float* Bs[2] = { gsm + 2*128*G_ALD, gsm + 2*128*G_ALD + 32 * G_BLD };
    float* Brep  = gsm + 2*128*G_ALD + 2*32*G_BLD;   // [16][G_BLD]

    const int tid  = threadIdx.x;
    const int wid  = tid >> 5;
    const int wmi  = wid & 3;
    const int wni  = wid >> 2;
    const int m0   = blockIdx.y * 128;
    const int n0   = blockIdx.x * 128;

    // Bias replication tile -> accumulator init
    for (int i = tid; i < 16 * 128; i += 256) {
        int r = i >> 7, c = i & 127;
        Brep[r * G_BLD + c] = bias[n0 + c];
    }
    __syncthreads();

    wm::fragment<wm::accumulator, 16, 16, 8, float> acc[2][4];
#pragma unroll
    for (int mi = 0; mi < 2; ++mi)
#pragma unroll
        for (int ni = 0; ni < 4; ++ni)
            wm::load_matrix_sync(acc[mi][ni], Brep + wni * 64 + ni * 16, G_BLD,
                                 wm::mem_row_major);
    __syncthreads();

    float4 ra[4], rb[4];

    auto ldg_tiles = [&](int k0) {
#pragma unroll
        for (int t = 0; t < 4; ++t) {
            int f = tid + t * 256;
            int r = f >> 3, c4 = (f & 7) << 2;
            ra[t] = *(const float4*)(A + (size_t)(m0 + r) * K + k0 + c4);
        }
#pragma unroll
        for (int t = 0; t < 4; ++t) {
            int f = tid + t * 256;
            int r = f >> 5, c4 = (f & 31) << 2;
            rb[t] = *(const float4*)(B + (size_t)(k0 + r) * N + n0 + c4);
        }
    };
    auto sts_tiles = [&](int buf) {
        float* as = As[buf];
        float* bs = Bs[buf];
#pragma unroll
        for (int t = 0; t < 4; ++t) {
            int f = tid + t * 256;
            int r = f >> 3, c4 = (f & 7) << 2;
            float* d = as + r * G_ALD + c4;
            d[0] = wm::__float_to_tf32(ra[t].x);
            d[1] = wm::__float_to_tf32(ra[t].y);
            d[2] = wm::__float_to_tf32(ra[t].z);
            d[3] = wm::__float_to_tf32(ra[t].w);
        }
#pragma unroll
        for (int t = 0; t < 4; ++t) {
            int f = tid + t * 256;
            int r = f >> 5, c4 = (f & 31) << 2;
            float* d = bs + r * G_BLD + c4;
            d[0] = wm::__float_to_tf32(rb[t].x);
            d[1] = wm::__float_to_tf32(rb[t].y);
            d[2] = wm::__float_to_tf32(rb[t].z);
            d[3] = wm::__float_to_tf32(rb[t].w);
        }
    };

    ldg_tiles(0);
    sts_tiles(0);
    __syncthreads();

    int buf = 0;
    for (int k0 = 0; k0 < K; k0 += 32) {
        const bool has_next = (k0 + 32 < K);
        if (has_next) ldg_tiles(k0 + 32);   // overlap with mma below

#pragma unroll
        for (int ks = 0; ks < 4; ++ks) {
            wm::fragment<wm::matrix_a, 16, 16, 8, wm::precision::tf32, wm::row_major> af[2];
            wm::fragment<wm::matrix_b, 16, 16, 8, wm::precision::tf32, wm::row_major> bf[4];
#pragma unroll
            for (int mi = 0; mi < 2; ++mi)
                wm::load_matrix_sync(af[mi], As[buf] + (wmi * 32 + mi * 16) * G_ALD + ks * 8, G_ALD);
#pragma unroll
            for (int ni = 0; ni < 4; ++ni)
                wm::load_matrix_sync(bf[ni], Bs[buf] + (ks * 8) * G_BLD + wni * 64 + ni * 16, G_BLD);
#pragma unroll
            for (int mi = 0; mi < 2; ++mi)
#pragma unroll
                for (int ni = 0; ni < 4; ++ni)
                    wm::mma_sync(acc[mi][ni], af[mi], bf[ni], acc[mi][ni]);
        }

        if (has_next) sts_tiles(buf ^ 1);
        __syncthreads();
        buf ^= 1;
    }

    float* outp = (n0 < 1024) ? out0 : ((n0 < 2048) ? out1 : out2);
    const int nc = n0 & 1023;
#pragma unroll
    for (int mi = 0; mi < 2; ++mi)
#pragma unroll
        for (int ni = 0; ni < 4; ++ni) {
            float* p = outp + (size_t)(m0 + wmi * 32 + mi * 16) * 1024
                            + nc + wni * 64 + ni * 16;
            wm::store_matrix_sync(p, acc[mi][ni], 1024, wm::mem_row_major);
        }
}

// ---------------------------------------------------------------------------
// Flash attention (causal), TF32 WMMA, double-buffered K/V, O kept in smem
// with in-place alpha rescale (no Opart buffer). Br=Bc=64, hd=64, 256 thr.
// ---------------------------------------------------------------------------
#define FLD 72

__global__ __launch_bounds__(256) void flash_tf32_kernel(
    const float* __restrict__ Qg, const float* __restrict__ Kg,
    const float* __restrict__ Vg, float* __restrict__ yt)
{
    extern __shared__ float sm[];
    float* Qs    = sm;                     // [64][FLD]
    float* Ks[2] = { Qs + 64 * FLD,  Qs + 2 * 64 * FLD };
    float* Vs[2] = { Qs + 3 * 64 * FLD, Qs + 4 * 64 * FLD };
    float* Ss    = Qs + 5 * 64 * FLD;      // S then P(tf32)
    float* Oacc  = Qs + 6 * 64 * FLD;      // fp32 running O

    const int qt  = gridDim.x - 1 - blockIdx.x;   // longest-first
    const int bh  = blockIdx.y;
    const int tid = threadIdx.x;
    const int wid = tid >> 5;
    const int wmi = wid & 3;               // 16-row stripe
    const int wni = wid >> 2;              // 32-col half

    const int r   = tid >> 2;              // softmax row owned
    const int qq  = tid & 3;               // 16-col quarter

    const size_t head_off = (size_t)bh * 131072u;
    const float* qb = Qg + head_off + (size_t)qt * 4096u;

    // Load Q (scaled, tf32) + zero Oacc
    for (int f = tid; f < 1024; f += 256) {
        int rr = f >> 4, c4 = (f & 15) << 2;
        float4 t = *(const float4*)(qb + rr * 64 + c4);
        float* dst = Qs + rr * FLD + c4;
        dst[0] = wm::__float_to_tf32(t.x * 0.125f);
        dst[1] = wm::__float_to_tf32(t.y * 0.125f);
        dst[2] = wm::__float_to_tf32(t.z * 0.125f);
        dst[3] = wm::__float_to_tf32(t.w * 0.125f);
        float4 z = {0.f, 0.f, 0.f, 0.f};
        *(float4*)(Oacc + rr * FLD + c4) = z;
    }

    float4 rk[4], rv[4];
    auto ldg_kv = [&](int kt) {
        const float* kb = Kg + head_off + (size_t)kt * 4096u;
        const float* vb = Vg + head_off + (size_t)kt * 4096u;
#pragma unroll
        for (int t = 0; t < 4; ++t) {
            int f = tid + t * 256;
            int rr = f >> 4, c4 = (f & 15) << 2;
            rk[t] = *(const float4*)(kb + rr * 64 + c4);
            rv[t] = *(const float4*)(vb + rr * 64 + c4);
        }
    };
    auto sts_kv = [&](int buf) {
#pragma unroll
        for (int t = 0; t < 4; ++t) {
            int f = tid + t * 256;
            int rr = f >> 4, c4 = (f & 15) << 2;
            float* dk = Ks[buf] + rr * FLD + c4;
            dk[0] = wm::__float_to_tf32(rk[t].x); dk[1] = wm::__float_to_tf32(rk[t].y);
            dk[2] = wm::__float_to_tf32(rk[t].z); dk[3] = wm::__float_to_tf32(rk[t].w);
            float* dv = Vs[buf] + rr * FLD + c4;
            dv[0] = wm::__float_to_tf32(rv[t].x); dv[1] = wm::__float_to_tf32(rv[t].y);
            dv[2] = wm::__float_to_tf32(rv[t].z); dv[3] = wm::__float_to_tf32(rv[t].w);
        }
    };

    ldg_kv(0);
    sts_kv(0);
    __syncthreads();

    float mrow = -1e30f, lrow = 0.0f;
    int buf = 0;

    for (int kt = 0; kt <= qt; ++kt) {
        const bool has_next = (kt < qt);
        if (has_next) ldg_kv(kt + 1);      // overlap with S-mma + softmax

        // ---- S = Q @ K^T ----
        {
            wm::fragment<wm::accumulator, 16, 16, 8, float> sacc[2];
#pragma unroll
            for (int ni = 0; ni < 2; ++ni) wm::fill_fragment(sacc[ni], 0.0f);
#pragma unroll
            for (int ks = 0; ks < 8; ++ks) {
                wm::fragment<wm::matrix_a, 16, 16, 8, wm::precision::tf32, wm::row_major> af;
                wm::fragment<wm::matrix_b, 16, 16, 8, wm::precision::tf32, wm::col_major> bf[2];
                wm::load_matrix_sync(af, Qs + (wmi * 16) * FLD + ks * 8, FLD);
#pragma unroll
                for (int ni = 0; ni < 2; ++ni)
                    wm::load_matrix_sync(bf[ni], Ks[buf] + (wni * 32 + ni * 16) * FLD + ks * 8, FLD);
#pragma unroll
                for (int ni = 0; ni < 2; ++ni)
                    wm::mma_sync(sacc[ni], af, bf[ni], sacc[ni]);
            }
#pragma unroll
            for (int ni = 0; ni < 2; ++ni)
                wm::store_matrix_sync(Ss + (wmi * 16) * FLD + wni * 32 + ni * 16,
                                      sacc[ni], FLD, wm::mem_row_major);
        }
        __syncthreads();

        // ---- Online softmax + in-place O rescale (row r, cols qq*16..) ----
        {
            float* srow = Ss + r * FLD + qq * 16;
            float s[16];
            const bool diag = (kt == qt);
#pragma unroll
            for (int j4 = 0; j4 < 4; ++j4) {
                float4 v = *(const float4*)(srow + j4 * 4);
                s[j4*4+0] = v.x; s[j4*4+1] = v.y; s[j4*4+2] = v.z; s[j4*4+3] = v.w;
            }
            if (diag) {
#pragma unroll
                for (int j = 0; j < 16; ++j)
                    if (qq * 16 + j > r) s[j] = -1e30f;
            }
            float mx = -1e30f;
#pragma unroll
            for (int j = 0; j < 16; ++j) mx = fmaxf(mx, s[j]);
            mx = fmaxf(mx, __shfl_xor_sync(0xffffffffu, mx, 1));
            mx = fmaxf(mx, __shfl_xor_sync(0xffffffffu, mx, 2));

            float mn = fmaxf(mrow, mx);
            float alpha = __expf(mrow - mn);
            mrow = mn;

            float sum = 0.0f;
#pragma unroll
            for (int j = 0; j < 16; ++j) {
                float p = __expf(s[j] - mn);
                sum += p;
                s[j] = wm::__float_to_tf32(p);
            }
#pragma unroll
            for (int j4 = 0; j4 < 4; ++j4) {
                float4 v = { s[j4*4+0], s[j4*4+1], s[j4*4+2], s[j4*4+3] };
                *(float4*)(srow + j4 * 4) = v;
            }
            sum += __shfl_xor_sync(0xffffffffu, sum, 1);
            sum += __shfl_xor_sync(0xffffffffu, sum, 2);
            lrow = lrow * alpha + sum;

            // scale running O row in place
            float* oa = Oacc + r * FLD + qq * 16;
#pragma unroll
            for (int j4 = 0; j4 < 4; ++j4) {
                float4 a = *(float4*)(oa + j4 * 4);
                a.x *= alpha; a.y *= alpha; a.z *= alpha; a.w *= alpha;
                *(float4*)(oa + j4 * 4) = a;
            }
        }
        __syncthreads();

        // ---- Oacc += P @ V (accumulate directly into Oacc fragments) ----
        {
            wm::fragment<wm::accumulator, 16, 16, 8, float> oacc[2];
#pragma unroll
            for (int ni = 0; ni < 2; ++ni)
                wm::load_matrix_sync(oacc[ni],
                    Oacc + (wmi * 16) * FLD + wni * 32 + ni * 16, FLD, wm::mem_row_major);
#pragma unroll
            for (int ks = 0; ks < 8; ++ks) {
                wm::fragment<wm::matrix_a, 16, 16, 8, wm::precision::tf32, wm::row_major> af;
                wm::fragment<wm::matrix_b, 16, 16, 8, wm::precision::tf32, wm::row_major> bf[2];
                wm::load_matrix_sync(af, Ss + (wmi * 16) * FLD + ks * 8, FLD);
#pragma unroll
                for (int ni = 0; ni < 2; ++ni)
                    wm::load_matrix_sync(bf[ni], Vs[buf] + (ks * 8) * FLD + wni * 32 + ni * 16, FLD);
#pragma unroll
                for (int ni = 0; ni < 2; ++ni)
                    wm::mma_sync(oacc[ni], af, bf[ni], oacc[ni]);
            }
#pragma unroll
            for (int ni = 0; ni < 2; ++ni)
                wm::store_matrix_sync(Oacc + (wmi * 16) * FLD + wni * 32 + ni * 16,
                                      oacc[ni], FLD, wm::mem_row_major);
        }

        if (has_next) sts_kv(buf ^ 1);
        __syncthreads();
        buf ^= 1;
    }

    // ---- Epilogue: normalize, write to [B, T, H, hd] ----
    {
        const int b = bh >> 4;
        const int h = bh & 15;
        const float inv = 1.0f / lrow;
        const int tq = qt * 64 + r;
        float* oa = Oacc + r * FLD + qq * 16;
        float* dst = yt + ((size_t)(b * 2048 + tq)) * 1024u + h * 64 + qq * 16;
#pragma unroll
        for (int j4 = 0; j4 < 4; ++j4) {
            float4 a = *(float4*)(oa + j4 * 4);
            a.x *= inv; a.y *= inv; a.z *= inv; a.w *= inv;
            *(float4*)(dst + j4 * 4) = a;
        }
    }
}

// ---------------------------------------------------------------------------
// Launch
// ---------------------------------------------------------------------------
extern "C" void kernel_launch(void* const* d_in, const int* in_sizes, int n_in,
                              void* d_out, int out_size)
{
    const float* x     = (const float*)d_in[0];
    const float* Wqkv  = (const float*)d_in[1];
    const float* bqkv  = (const float*)d_in[2];
    const float* Wproj = (const float*)d_in[3];
    const float* bproj = (const float*)d_in[4];
    float* out = (float*)d_out;

    float *q, *k, *v, *yt;
    cudaGetSymbolAddress((void**)&q,  g_q);
    cudaGetSymbolAddress((void**)&k,  g_k);
    cudaGetSymbolAddress((void**)&v,  g_v);
    cudaGetSymbolAddress((void**)&yt, g_yt);

    const int M = 2 * 2048;   // 4096
    const int C = 1024;

    const int gemm_smem = (2 * 128 * G_ALD + 2 * 32 * G_BLD + 16 * G_BLD)
                          * (int)sizeof(float);   // 84,480 B
    cudaFuncSetAttribute(gemm_tf32_kernel,
                         cudaFuncAttributeMaxDynamicSharedMemorySize, gemm_smem);

    // 1) QKV projection
    {
        dim3 grid(3 * C / 128, M / 128);   // (24, 32)
        gemm_tf32_kernel<<<grid, 256, gemm_smem>>>(x, Wqkv, bqkv, q, k, v, M, 3 * C, C);
    }

    // 2) Flash attention (causal)
    {
        const int smem = 7 * 64 * FLD * (int)sizeof(float);   // 129,024 B
        cudaFuncSetAttribute(flash_tf32_kernel,
                             cudaFuncAttributeMaxDynamicSharedMemorySize, smem);
        dim3 grid(2048 / 64, 32);
        flash_tf32_kernel<<<grid, 256, smem>>>(q, k, v, yt);
    }

    // 3) Output projection
    {
        dim3 grid(C / 128, M / 128);       // (8, 32)
        gemm_tf32_kernel<<<grid, 256, gemm_smem>>>(yt, Wproj, bproj, out, out, out, M, C, C);
    }
}

// round 6
// speedup vs baseline: 1.1740x; 1.1740x over previous
#include <cuda_runtime.h>
#include <mma.h>
#include <cstdint>

namespace wm = nvcuda::wmma;

// ---------------------------------------------------------------------------
// Scratch (device globals)
// ---------------------------------------------------------------------------
__device__ float g_q [2u * 2048u * 1024u];
__device__ float g_k [2u * 2048u * 1024u];
__device__ float g_v [2u * 2048u * 1024u];
__device__ float g_yt[2u * 2048u * 1024u];
__device__ float g_xr   [4096u * 1024u];   // tf32-rounded x
__device__ float g_wqkvr[1024u * 3072u];   // tf32-rounded Wqkv
__device__ float g_wprojr[1024u * 1024u];  // tf32-rounded Wproj

// ---------------------------------------------------------------------------
// cp.async helpers
// ---------------------------------------------------------------------------
__device__ __forceinline__ uint32_t smem_u32(const void* p) {
    return (uint32_t)__cvta_generic_to_shared(p);
}
__device__ __forceinline__ void cp16(uint32_t dst, const void* src) {
    asm volatile("cp.async.cg.shared.global [%0], [%1], 16;"
                 :: "r"(dst), "l"(src) : "memory");
}
__device__ __forceinline__ void cp_commit() {
    asm volatile("cp.async.commit_group;" ::: "memory");
}
template <int N>
__device__ __forceinline__ void cp_wait() {
    asm volatile("cp.async.wait_group %0;" :: "n"(N) : "memory");
}

// ---------------------------------------------------------------------------
// Elementwise tf32 rounding pass (float4)
// ---------------------------------------------------------------------------
__global__ void round_tf32_kernel(const float* __restrict__ in,
                                  float* __restrict__ out, int n4)
{
    int i = blockIdx.x * blockDim.x + threadIdx.x;
    if (i < n4) {
        float4 v = ((const float4*)in)[i];
        v.x = wm::__float_to_tf32(v.x); v.y = wm::__float_to_tf32(v.y);
        v.z = wm::__float_to_tf32(v.z); v.w = wm::__float_to_tf32(v.w);
        ((float4*)out)[i] = v;
    }
}

// ---------------------------------------------------------------------------
// TF32 WMMA GEMM with 3-stage cp.async pipeline.
// C = A[M,K] @ B[K,N] + bias[N]. BM=BN=128, BK=32, 256 thr (8 warps 4x2).
// A and B must be pre-rounded to tf32. If ROUND_OUT, output is tf32-rounded.
// Output routed into one of 3 width-1024 buffers (QKV split).
// ---------------------------------------------------------------------------
#define G_ALD 40
#define G_BLD 136
#define G_ASZ (128 * G_ALD)
#define G_BSZ (32 * G_BLD)
#define G_STG 3

__global__ __launch_bounds__(256) void gemm_tf32_kernel(
    const float* __restrict__ A, const float* __restrict__ B,
    const float* __restrict__ bias,
    float* __restrict__ out0, float* __restrict__ out1, float* __restrict__ out2,
    int M, int N, int K, int round_out)
{
    extern __shared__ float gsm[];
    float* Brep = gsm + G_STG * (G_ASZ + G_BSZ);   // [16][G_BLD]

    const int tid  = threadIdx.x;
    const int wid  = tid >> 5;
    const int wmi  = wid & 3;
    const int wni  = wid >> 2;
    const int m0   = blockIdx.y * 128;
    const int n0   = blockIdx.x * 128;

    // Bias replication tile -> accumulator init
    for (int i = tid; i < 16 * 128; i += 256) {
        int r = i >> 7, c = i & 127;
        Brep[r * G_BLD + c] = bias[n0 + c];
    }
    __syncthreads();

    wm::fragment<wm::accumulator, 16, 16, 8, float> acc[2][4];
#pragma unroll
    for (int mi = 0; mi < 2; ++mi)
#pragma unroll
        for (int ni = 0; ni < 4; ++ni)
            wm::load_matrix_sync(acc[mi][ni], Brep + wni * 64 + ni * 16, G_BLD,
                                 wm::mem_row_major);

    const int iters = K >> 5;    // K/32

    auto issue_stage = [&](int stage) {
        const int s = stage % G_STG;
        const int k0 = stage << 5;
        float* as = gsm + s * G_ASZ;
        float* bs = gsm + G_STG * G_ASZ + s * G_BSZ;
#pragma unroll
        for (int t = 0; t < 4; ++t) {
            int f = tid + t * 256;
            int r = f >> 3, c4 = (f & 7) << 2;
            cp16(smem_u32(as + r * G_ALD + c4),
                 A + (size_t)(m0 + r) * K + k0 + c4);
        }
#pragma unroll
        for (int t = 0; t < 4; ++t) {
            int f = tid + t * 256;
            int r = f >> 5, c4 = (f & 31) << 2;
            cp16(smem_u32(bs + r * G_BLD + c4),
                 B + (size_t)(k0 + r) * N + n0 + c4);
        }
        cp_commit();
    };

    issue_stage(0);
    issue_stage(1);

    for (int it = 0; it < iters; ++it) {
        cp_wait<1>();          // stage `it` resident
        __syncthreads();       // visible to all + all done with buffer (it+2)%3

        if (it + 2 < iters) issue_stage(it + 2);
        else                cp_commit();          // empty group, keeps count uniform

        const int s = it % G_STG;
        const float* as = gsm + s * G_ASZ;
        const float* bs = gsm + G_STG * G_ASZ + s * G_BSZ;
#pragma unroll
        for (int ks = 0; ks < 4; ++ks) {
            wm::fragment<wm::matrix_a, 16, 16, 8, wm::precision::tf32, wm::row_major> af[2];
            wm::fragment<wm::matrix_b, 16, 16, 8, wm::precision::tf32, wm::row_major> bf[4];
#pragma unroll
            for (int mi = 0; mi < 2; ++mi)
                wm::load_matrix_sync(af[mi], as + (wmi * 32 + mi * 16) * G_ALD + ks * 8, G_ALD);
#pragma unroll
            for (int ni = 0; ni < 4; ++ni)
                wm::load_matrix_sync(bf[ni], bs + (ks * 8) * G_BLD + wni * 64 + ni * 16, G_BLD);
#pragma unroll
            for (int mi = 0; mi < 2; ++mi)
#pragma unroll
                for (int ni = 0; ni < 4; ++ni)
                    wm::mma_sync(acc[mi][ni], af[mi], bf[ni], acc[mi][ni]);
        }
        __syncthreads();
    }

    // Epilogue via smem staging not needed: store fragments, optionally round.
    float* outp = (n0 < 1024) ? out0 : ((n0 < 2048) ? out1 : out2);
    const int nc = n0 & 1023;
    if (round_out) {
#pragma unroll
        for (int mi = 0; mi < 2; ++mi)
#pragma unroll
            for (int ni = 0; ni < 4; ++ni) {
#pragma unroll
                for (int e = 0; e < acc[mi][ni].num_elements; ++e)
                    acc[mi][ni].x[e] = wm::__float_to_tf32(acc[mi][ni].x[e]);
                float* p = outp + (size_t)(m0 + wmi * 32 + mi * 16) * 1024
                                + nc + wni * 64 + ni * 16;
                wm::store_matrix_sync(p, acc[mi][ni], 1024, wm::mem_row_major);
            }
    } else {
#pragma unroll
        for (int mi = 0; mi < 2; ++mi)
#pragma unroll
            for (int ni = 0; ni < 4; ++ni) {
                float* p = outp + (size_t)(m0 + wmi * 32 + mi * 16) * 1024
                                + nc + wni * 64 + ni * 16;
                wm::store_matrix_sync(p, acc[mi][ni], 1024, wm::mem_row_major);
            }
    }
}

// ---------------------------------------------------------------------------
// Flash attention (causal), TF32 WMMA, cp.async double-buffered K/V.
// Br=Bc=64, hd=64, 256 threads. Q/K/V are pre-rounded tf32 (from GEMM1).
// Output yt written tf32-rounded in [B,T,H,hd] layout.
// ---------------------------------------------------------------------------
#define FLD 72
#define F_TSZ (64 * FLD)

__global__ __launch_bounds__(256) void flash_tf32_kernel(
    const float* __restrict__ Qg, const float* __restrict__ Kg,
    const float* __restrict__ Vg, float* __restrict__ yt)
{
    extern __shared__ float sm[];
    float* Qs    = sm;
    float* Ks0   = Qs   + F_TSZ;
    float* Ks1   = Ks0  + F_TSZ;
    float* Vs0   = Ks1  + F_TSZ;
    float* Vs1   = Vs0  + F_TSZ;
    float* Ss    = Vs1  + F_TSZ;
    float* Oacc  = Ss   + F_TSZ;
    float* Opart = Oacc + F_TSZ;
    float* alphaS= Opart+ F_TSZ;
    float* KsA[2] = { Ks0, Ks1 };
    float* VsA[2] = { Vs0, Vs1 };

    const int qt  = gridDim.x - 1 - blockIdx.x;   // longest-first
    const int bh  = blockIdx.y;
    const int tid = threadIdx.x;
    const int wid = tid >> 5;
    const int wmi = wid & 3;
    const int wni = wid >> 2;

    const int r   = tid >> 2;
    const int qq  = tid & 3;

    const size_t head_off = (size_t)bh * 131072u;
    const float* qb = Qg + head_off + (size_t)qt * 4096u;

    auto issue_kv = [&](int kt, int buf) {
        const float* kb = Kg + head_off + (size_t)kt * 4096u;
        const float* vb = Vg + head_off + (size_t)kt * 4096u;
        float* dk = KsA[buf];
        float* dv = VsA[buf];
#pragma unroll
        for (int t = 0; t < 4; ++t) {
            int f = tid + t * 256;
            int rr = f >> 4, c4 = (f & 15) << 2;
            cp16(smem_u32(dk + rr * FLD + c4), kb + rr * 64 + c4);
            cp16(smem_u32(dv + rr * FLD + c4), vb + rr * 64 + c4);
        }
        cp_commit();
    };

    issue_kv(0, 0);

    // Load Q tile (pre-rounded; *0.125 is exact) + zero Oacc
    for (int f = tid; f < 1024; f += 256) {
        int rr = f >> 4, c4 = (f & 15) << 2;
        float4 t = *(const float4*)(qb + rr * 64 + c4);
        float* dst = Qs + rr * FLD + c4;
        dst[0] = t.x * 0.125f; dst[1] = t.y * 0.125f;
        dst[2] = t.z * 0.125f; dst[3] = t.w * 0.125f;
        float4 z = {0.f, 0.f, 0.f, 0.f};
        *(float4*)(Oacc + rr * FLD + c4) = z;
    }

    float mrow = -1e30f, lrow = 0.0f;
    int buf = 0;

    for (int kt = 0; kt <= qt; ++kt) {
        cp_wait<0>();          // K/V for kt resident
        __syncthreads();

        if (kt < qt) issue_kv(kt + 1, buf ^ 1);   // overlaps all of this iter

        // ---- S = Q @ K^T ----
        {
            wm::fragment<wm::accumulator, 16, 16, 8, float> sacc[2];
#pragma unroll
            for (int ni = 0; ni < 2; ++ni) wm::fill_fragment(sacc[ni], 0.0f);
#pragma unroll
            for (int ks = 0; ks < 8; ++ks) {
                wm::fragment<wm::matrix_a, 16, 16, 8, wm::precision::tf32, wm::row_major> af;
                wm::fragment<wm::matrix_b, 16, 16, 8, wm::precision::tf32, wm::col_major> bf[2];
                wm::load_matrix_sync(af, Qs + (wmi * 16) * FLD + ks * 8, FLD);
#pragma unroll
                for (int ni = 0; ni < 2; ++ni)
                    wm::load_matrix_sync(bf[ni], KsA[buf] + (wni * 32 + ni * 16) * FLD + ks * 8, FLD);
#pragma unroll
                for (int ni = 0; ni < 2; ++ni)
                    wm::mma_sync(sacc[ni], af, bf[ni], sacc[ni]);
            }
#pragma unroll
            for (int ni = 0; ni < 2; ++ni)
                wm::store_matrix_sync(Ss + (wmi * 16) * FLD + wni * 32 + ni * 16,
                                      sacc[ni], FLD, wm::mem_row_major);
        }
        __syncthreads();

        // ---- Online softmax (row r, cols qq*16..qq*16+15) ----
        {
            float s[16];
            float* srow = Ss + r * FLD + qq * 16;
            const bool diag = (kt == qt);
#pragma unroll
            for (int j = 0; j < 16; ++j) {
                float v = srow[j];
                if (diag && (qq * 16 + j > r)) v = -1e30f;
                s[j] = v;
            }
            float mx = -1e30f;
#pragma unroll
            for (int j = 0; j < 16; ++j) mx = fmaxf(mx, s[j]);
            mx = fmaxf(mx, __shfl_xor_sync(0xffffffffu, mx, 1));
            mx = fmaxf(mx, __shfl_xor_sync(0xffffffffu, mx, 2));

            float mn = fmaxf(mrow, mx);
            float alpha = __expf(mrow - mn);
            mrow = mn;

            float sum = 0.0f;
#pragma unroll
            for (int j = 0; j < 16; ++j) {
                float p = __expf(s[j] - mn);
                sum += p;
                srow[j] = wm::__float_to_tf32(p);
            }
            sum += __shfl_xor_sync(0xffffffffu, sum, 1);
            sum += __shfl_xor_sync(0xffffffffu, sum, 2);
            lrow = lrow * alpha + sum;
            if (qq == 0) alphaS[r] = alpha;
        }
        __syncthreads();

        // ---- Opart = P @ V ----
        {
            wm::fragment<wm::accumulator, 16, 16, 8, float> oacc[2];
#pragma unroll
            for (int ni = 0; ni < 2; ++ni) wm::fill_fragment(oacc[ni], 0.0f);
#pragma unroll
            for (int ks = 0; ks < 8; ++ks) {
                wm::fragment<wm::matrix_a, 16, 16, 8, wm::precision::tf32, wm::row_major> af;
                wm::fragment<wm::matrix_b, 16, 16, 8, wm::precision::tf32, wm::row_major> bf[2];
                wm::load_matrix_sync(af, Ss + (wmi * 16) * FLD + ks * 8, FLD);
#pragma unroll
                for (int ni = 0; ni < 2; ++ni)
                    wm::load_matrix_sync(bf[ni], VsA[buf] + (ks * 8) * FLD + wni * 32 + ni * 16, FLD);
#pragma unroll
                for (int ni = 0; ni < 2; ++ni)
                    wm::mma_sync(oacc[ni], af, bf[ni], oacc[ni]);
            }
#pragma unroll
            for (int ni = 0; ni < 2; ++ni)
                wm::store_matrix_sync(Opart + (wmi * 16) * FLD + wni * 32 + ni * 16,
                                      oacc[ni], FLD, wm::mem_row_major);
        }
        __syncthreads();

        // ---- O update ----
        {
            float alpha = alphaS[r];
            float* oa = Oacc  + r * FLD + qq * 16;
            float* op = Opart + r * FLD + qq * 16;
#pragma unroll
            for (int j4 = 0; j4 < 4; ++j4) {
                float4 a = *(float4*)(oa + j4 * 4);
                float4 p = *(float4*)(op + j4 * 4);
                a.x = a.x * alpha + p.x; a.y = a.y * alpha + p.y;
                a.z = a.z * alpha + p.z; a.w = a.w * alpha + p.w;
                *(float4*)(oa + j4 * 4) = a;
            }
        }
        __syncthreads();
        buf ^= 1;
    }

    // ---- Epilogue: normalize, round to tf32, write [B,T,H,hd] ----
    {
        const int b = bh >> 4;
        const int h = bh & 15;
        const float inv = 1.0f / lrow;
        const int tq = qt * 64 + r;
        float* oa = Oacc + r * FLD + qq * 16;
        float* dst = yt + ((size_t)(b * 2048 + tq)) * 1024u + h * 64 + qq * 16;
#pragma unroll
        for (int j4 = 0; j4 < 4; ++j4) {
            float4 a = *(float4*)(oa + j4 * 4);
            a.x = wm::__float_to_tf32(a.x * inv);
            a.y = wm::__float_to_tf32(a.y * inv);
            a.z = wm::__float_to_tf32(a.z * inv);
            a.w = wm::__float_to_tf32(a.w * inv);
            *(float4*)(dst + j4 * 4) = a;
        }
    }
}

// ---------------------------------------------------------------------------
// Launch
// ---------------------------------------------------------------------------
extern "C" void kernel_launch(void* const* d_in, const int* in_sizes, int n_in,
                              void* d_out, int out_size)
{
    const float* x     = (const float*)d_in[0];
    const float* Wqkv  = (const float*)d_in[1];
    const float* bqkv  = (const float*)d_in[2];
    const float* Wproj = (const float*)d_in[3];
    const float* bproj = (const float*)d_in[4];
    float* out = (float*)d_out;

    float *q, *k, *v, *yt, *xr, *wqkvr, *wprojr;
    cudaGetSymbolAddress((void**)&q,  g_q);
    cudaGetSymbolAddress((void**)&k,  g_k);
    cudaGetSymbolAddress((void**)&v,  g_v);
    cudaGetSymbolAddress((void**)&yt, g_yt);
    cudaGetSymbolAddress((void**)&xr, g_xr);
    cudaGetSymbolAddress((void**)&wqkvr, g_wqkvr);
    cudaGetSymbolAddress((void**)&wprojr, g_wprojr);

    const int M = 4096, C = 1024;

    // 0) tf32 pre-round passes
    {
        int n4 = (M * C) / 4;
        round_tf32_kernel<<<(n4 + 255) / 256, 256>>>(x, xr, n4);
        n4 = (C * 3 * C) / 4;
        round_tf32_kernel<<<(n4 + 255) / 256, 256>>>(Wqkv, wqkvr, n4);
        n4 = (C * C) / 4;
        round_tf32_kernel<<<(n4 + 255) / 256, 256>>>(Wproj, wprojr, n4);
    }

    const int gemm_smem = (G_STG * (G_ASZ + G_BSZ) + 16 * G_BLD) * (int)sizeof(float);
    cudaFuncSetAttribute(gemm_tf32_kernel,
                         cudaFuncAttributeMaxDynamicSharedMemorySize, gemm_smem);

    // 1) QKV projection (tf32-rounded outputs)
    {
        dim3 grid(3 * C / 128, M / 128);   // (24, 32)
        gemm_tf32_kernel<<<grid, 256, gemm_smem>>>(xr, wqkvr, bqkv, q, k, v,
                                                   M, 3 * C, C, 1);
    }

    // 2) Flash attention (causal) -> yt (tf32-rounded)
    {
        const int smem = (8 * F_TSZ + 64) * (int)sizeof(float);   // 147,712 B
        cudaFuncSetAttribute(flash_tf32_kernel,
                             cudaFuncAttributeMaxDynamicSharedMemorySize, smem);
        dim3 grid(2048 / 64, 32);
        flash_tf32_kernel<<<grid, 256, smem>>>(q, k, v, yt);
    }

    // 3) Output projection (fp32 output)
    {
        dim3 grid(C / 128, M / 128);       // (8, 32)
        gemm_tf32_kernel<<<grid, 256, gemm_smem>>>(yt, wprojr, bproj,
                                                   out, out, out, M, C, C, 0);
    }
}

// round 7
// speedup vs baseline: 1.2589x; 1.0723x over previous
#include <cuda_runtime.h>
#include <mma.h>
#include <cstdint>

namespace wm = nvcuda::wmma;

// ---------------------------------------------------------------------------
// Scratch (device globals)
// ---------------------------------------------------------------------------
__device__ float g_q [2u * 2048u * 1024u];
__device__ float g_k [2u * 2048u * 1024u];
__device__ float g_v [2u * 2048u * 1024u];
__device__ float g_yt[2u * 2048u * 1024u];
__device__ float g_xr   [4096u * 1024u];
__device__ float g_wqkvr[1024u * 3072u];
__device__ float g_wprojr[1024u * 1024u];

// ---------------------------------------------------------------------------
// cp.async helpers
// ---------------------------------------------------------------------------
__device__ __forceinline__ uint32_t smem_u32(const void* p) {
    return (uint32_t)__cvta_generic_to_shared(p);
}
__device__ __forceinline__ void cp16(uint32_t dst, const void* src) {
    asm volatile("cp.async.cg.shared.global [%0], [%1], 16;"
                 :: "r"(dst), "l"(src) : "memory");
}
__device__ __forceinline__ void cp_commit() {
    asm volatile("cp.async.commit_group;" ::: "memory");
}
template <int N>
__device__ __forceinline__ void cp_wait() {
    asm volatile("cp.async.wait_group %0;" :: "n"(N) : "memory");
}

// ---------------------------------------------------------------------------
// Elementwise tf32 rounding pass (float4)
// ---------------------------------------------------------------------------
__global__ void round_tf32_kernel(const float* __restrict__ in,
                                  float* __restrict__ out, int n4)
{
    int i = blockIdx.x * blockDim.x + threadIdx.x;
    if (i < n4) {
        float4 v = ((const float4*)in)[i];
        v.x = wm::__float_to_tf32(v.x); v.y = wm::__float_to_tf32(v.y);
        v.z = wm::__float_to_tf32(v.z); v.w = wm::__float_to_tf32(v.w);
        ((float4*)out)[i] = v;
    }
}

// ---------------------------------------------------------------------------
// TF32 WMMA GEMM, 2-stage cp.async, 2 CTAs/SM.
// C = A[M,K] @ B[K,N] + bias[N]. BM=BN=128, BK=32, 256 thr (8 warps 4x2).
// ---------------------------------------------------------------------------
#define G_ALD 40
#define G_BLD 136
#define G_ASZ (128 * G_ALD)
#define G_BSZ (32 * G_BLD)
#define G_STG 2

__global__ __launch_bounds__(256, 2) void gemm_tf32_kernel(
    const float* __restrict__ A, const float* __restrict__ B,
    const float* __restrict__ bias,
    float* __restrict__ out0, float* __restrict__ out1, float* __restrict__ out2,
    int M, int N, int K, int round_out)
{
    extern __shared__ float gsm[];
    float* Brep = gsm + G_STG * (G_ASZ + G_BSZ);

    const int tid  = threadIdx.x;
    const int wid  = tid >> 5;
    const int wmi  = wid & 3;
    const int wni  = wid >> 2;
    const int m0   = blockIdx.y * 128;
    const int n0   = blockIdx.x * 128;

    for (int i = tid; i < 16 * 128; i += 256) {
        int r = i >> 7, c = i & 127;
        Brep[r * G_BLD + c] = bias[n0 + c];
    }
    __syncthreads();

    wm::fragment<wm::accumulator, 16, 16, 8, float> acc[2][4];
#pragma unroll
    for (int mi = 0; mi < 2; ++mi)
#pragma unroll
        for (int ni = 0; ni < 4; ++ni)
            wm::load_matrix_sync(acc[mi][ni], Brep + wni * 64 + ni * 16, G_BLD,
                                 wm::mem_row_major);

    const int iters = K >> 5;

    auto issue_stage = [&](int stage) {
        const int s = stage & 1;
        const int k0 = stage << 5;
        float* as = gsm + s * G_ASZ;
        float* bs = gsm + G_STG * G_ASZ + s * G_BSZ;
#pragma unroll
        for (int t = 0; t < 4; ++t) {
            int f = tid + t * 256;
            int r = f >> 3, c4 = (f & 7) << 2;
            cp16(smem_u32(as + r * G_ALD + c4),
                 A + (size_t)(m0 + r) * K + k0 + c4);
        }
#pragma unroll
        for (int t = 0; t < 4; ++t) {
            int f = tid + t * 256;
            int r = f >> 5, c4 = (f & 31) << 2;
            cp16(smem_u32(bs + r * G_BLD + c4),
                 B + (size_t)(k0 + r) * N + n0 + c4);
        }
        cp_commit();
    };

    issue_stage(0);
    issue_stage(1);

    for (int it = 0; it < iters; ++it) {
        cp_wait<1>();
        __syncthreads();

        const int s = it & 1;
        const float* as = gsm + s * G_ASZ;
        const float* bs = gsm + G_STG * G_ASZ + s * G_BSZ;
#pragma unroll
        for (int ks = 0; ks < 4; ++ks) {
            wm::fragment<wm::matrix_a, 16, 16, 8, wm::precision::tf32, wm::row_major> af[2];
            wm::fragment<wm::matrix_b, 16, 16, 8, wm::precision::tf32, wm::row_major> bf[4];
#pragma unroll
            for (int mi = 0; mi < 2; ++mi)
                wm::load_matrix_sync(af[mi], as + (wmi * 32 + mi * 16) * G_ALD + ks * 8, G_ALD);
#pragma unroll
            for (int ni = 0; ni < 4; ++ni)
                wm::load_matrix_sync(bf[ni], bs + (ks * 8) * G_BLD + wni * 64 + ni * 16, G_BLD);
#pragma unroll
            for (int mi = 0; mi < 2; ++mi)
#pragma unroll
                for (int ni = 0; ni < 4; ++ni)
                    wm::mma_sync(acc[mi][ni], af[mi], bf[ni], acc[mi][ni]);
        }
        __syncthreads();

        if (it + 2 < iters) issue_stage(it + 2);
        else                cp_commit();   // empty group keeps accounting uniform
    }

    float* outp = (n0 < 1024) ? out0 : ((n0 < 2048) ? out1 : out2);
    const int nc = n0 & 1023;
#pragma unroll
    for (int mi = 0; mi < 2; ++mi)
#pragma unroll
        for (int ni = 0; ni < 4; ++ni) {
            if (round_out) {
#pragma unroll
                for (int e = 0; e < acc[mi][ni].num_elements; ++e)
                    acc[mi][ni].x[e] = wm::__float_to_tf32(acc[mi][ni].x[e]);
            }
            float* p = outp + (size_t)(m0 + wmi * 32 + mi * 16) * 1024
                            + nc + wni * 64 + ni * 16;
            wm::store_matrix_sync(p, acc[mi][ni], 1024, wm::mem_row_major);
        }
}

// ---------------------------------------------------------------------------
// Flash attention (causal), TF32 WMMA. Br=128, Bc=64, hd=64, 512 threads.
// 16 warps: wmi=wid&3 (32-row stripe of 128), wni=wid>>2 (16-col stripe of 64).
// cp.async double-buffered K/V. PV accumulates into Oacc fragments directly.
// ---------------------------------------------------------------------------
#define FLD 72

__global__ __launch_bounds__(512) void flash_tf32_kernel(
    const float* __restrict__ Qg, const float* __restrict__ Kg,
    const float* __restrict__ Vg, float* __restrict__ yt)
{
    extern __shared__ float sm[];
    float* Qs    = sm;                        // [128][FLD]
    float* Ss    = Qs   + 128 * FLD;          // [128][FLD]
    float* Oacc  = Ss   + 128 * FLD;          // [128][FLD]
    float* Ks0   = Oacc + 128 * FLD;          // [64][FLD] x2
    float* Ks1   = Ks0  + 64 * FLD;
    float* Vs0   = Ks1  + 64 * FLD;
    float* Vs1   = Vs0  + 64 * FLD;
    float* KsA[2] = { Ks0, Ks1 };
    float* VsA[2] = { Vs0, Vs1 };

    const int qt  = gridDim.x - 1 - blockIdx.x;   // longest-first
    const int bh  = blockIdx.y;
    const int tid = threadIdx.x;
    const int wid = tid >> 5;
    const int wmi = wid & 3;
    const int wni = wid >> 2;

    const int r   = tid >> 2;        // softmax row owned (0..127)
    const int qq  = tid & 3;         // 16-col quarter of 64

    const size_t head_off = (size_t)bh * 131072u;
    const float* qb = Qg + head_off + (size_t)qt * 8192u;   // qt*128*64

    auto issue_kv = [&](int kt, int buf) {
        const float* kb = Kg + head_off + (size_t)kt * 4096u;
        const float* vb = Vg + head_off + (size_t)kt * 4096u;
        float* dk = KsA[buf];
        float* dv = VsA[buf];
#pragma unroll
        for (int t = 0; t < 2; ++t) {
            int f = tid + t * 512;
            int rr = f >> 4, c4 = (f & 15) << 2;
            cp16(smem_u32(dk + rr * FLD + c4), kb + rr * 64 + c4);
            cp16(smem_u32(dv + rr * FLD + c4), vb + rr * 64 + c4);
        }
        cp_commit();
    };

    issue_kv(0, 0);

    // Load Q tile (pre-rounded tf32; *0.125 exact) + zero Oacc
    for (int f = tid; f < 2048; f += 512) {
        int rr = f >> 4, c4 = (f & 15) << 2;
        float4 t = *(const float4*)(qb + rr * 64 + c4);
        float* dst = Qs + rr * FLD + c4;
        dst[0] = t.x * 0.125f; dst[1] = t.y * 0.125f;
        dst[2] = t.z * 0.125f; dst[3] = t.w * 0.125f;
        float4 z = {0.f, 0.f, 0.f, 0.f};
        *(float4*)(Oacc + rr * FLD + c4) = z;
    }

    float mrow = -1e30f, lrow = 0.0f;
    int buf = 0;
    const int n_kt = 2 * (qt + 1);

    for (int kt = 0; kt < n_kt; ++kt) {
        cp_wait<0>();
        __syncthreads();

        if (kt + 1 < n_kt) issue_kv(kt + 1, buf ^ 1);

        // ---- S = Q @ K^T : warp tile 32x16 ----
        {
            wm::fragment<wm::accumulator, 16, 16, 8, float> sacc[2];
#pragma unroll
            for (int mi = 0; mi < 2; ++mi) wm::fill_fragment(sacc[mi], 0.0f);
#pragma unroll
            for (int ks = 0; ks < 8; ++ks) {
                wm::fragment<wm::matrix_a, 16, 16, 8, wm::precision::tf32, wm::row_major> af[2];
                wm::fragment<wm::matrix_b, 16, 16, 8, wm::precision::tf32, wm::col_major> bf;
#pragma unroll
                for (int mi = 0; mi < 2; ++mi)
                    wm::load_matrix_sync(af[mi], Qs + (wmi * 32 + mi * 16) * FLD + ks * 8, FLD);
                wm::load_matrix_sync(bf, KsA[buf] + (wni * 16) * FLD + ks * 8, FLD);
#pragma unroll
                for (int mi = 0; mi < 2; ++mi)
                    wm::mma_sync(sacc[mi], af[mi], bf, sacc[mi]);
            }
#pragma unroll
            for (int mi = 0; mi < 2; ++mi)
                wm::store_matrix_sync(Ss + (wmi * 32 + mi * 16) * FLD + wni * 16,
                                      sacc[mi], FLD, wm::mem_row_major);
        }
        __syncthreads();

        // ---- Online softmax + in-place O rescale ----
        {
            float s[16];
            float* srow = Ss + r * FLD + qq * 16;
            const bool need_mask = (kt >= 2 * qt);
#pragma unroll
            for (int j = 0; j < 16; ++j) s[j] = srow[j];
            if (need_mask) {
                const int row_g = qt * 128 + r;
                const int col_g0 = kt * 64 + qq * 16;
#pragma unroll
                for (int j = 0; j < 16; ++j)
                    if (col_g0 + j > row_g) s[j] = -1e30f;
            }
            float mx = -1e30f;
#pragma unroll
            for (int j = 0; j < 16; ++j) mx = fmaxf(mx, s[j]);
            mx = fmaxf(mx, __shfl_xor_sync(0xffffffffu, mx, 1));
            mx = fmaxf(mx, __shfl_xor_sync(0xffffffffu, mx, 2));

            float mn = fmaxf(mrow, mx);
            float alpha = __expf(mrow - mn);
            mrow = mn;

            float sum = 0.0f;
#pragma unroll
            for (int j = 0; j < 16; ++j) {
                float p = __expf(s[j] - mn);
                sum += p;
                srow[j] = wm::__float_to_tf32(p);
            }
            sum += __shfl_xor_sync(0xffffffffu, sum, 1);
            sum += __shfl_xor_sync(0xffffffffu, sum, 2);
            lrow = lrow * alpha + sum;

            // scale running O row segment (16 cols) in place
            float* oa = Oacc + r * FLD + qq * 16;
#pragma unroll
            for (int j4 = 0; j4 < 4; ++j4) {
                float4 a = *(float4*)(oa + j4 * 4);
                a.x *= alpha; a.y *= alpha; a.z *= alpha; a.w *= alpha;
                *(float4*)(oa + j4 * 4) = a;
            }
        }
        __syncthreads();

        // ---- Oacc += P @ V ----
        {
            wm::fragment<wm::accumulator, 16, 16, 8, float> oacc[2];
#pragma unroll
            for (int mi = 0; mi < 2; ++mi)
                wm::load_matrix_sync(oacc[mi],
                    Oacc + (wmi * 32 + mi * 16) * FLD + wni * 16, FLD, wm::mem_row_major);
#pragma unroll
            for (int ks = 0; ks < 8; ++ks) {
                wm::fragment<wm::matrix_a, 16, 16, 8, wm::precision::tf32, wm::row_major> af[2];
                wm::fragment<wm::matrix_b, 16, 16, 8, wm::precision::tf32, wm::row_major> bf;
#pragma unroll
                for (int mi = 0; mi < 2; ++mi)
                    wm::load_matrix_sync(af[mi], Ss + (wmi * 32 + mi * 16) * FLD + ks * 8, FLD);
                wm::load_matrix_sync(bf, VsA[buf] + (ks * 8) * FLD + wni * 16, FLD);
#pragma unroll
                for (int mi = 0; mi < 2; ++mi)
                    wm::mma_sync(oacc[mi], af[mi], bf, oacc[mi]);
            }
#pragma unroll
            for (int mi = 0; mi < 2; ++mi)
                wm::store_matrix_sync(Oacc + (wmi * 32 + mi * 16) * FLD + wni * 16,
                                      oacc[mi], FLD, wm::mem_row_major);
        }
        __syncthreads();
        buf ^= 1;
    }

    // ---- Epilogue: normalize, round to tf32, write [B,T,H,hd] ----
    {
        const int b = bh >> 4;
        const int h = bh & 15;
        const float inv = 1.0f / lrow;
        const int tq = qt * 128 + r;
        float* oa = Oacc + r * FLD + qq * 16;
        float* dst = yt + ((size_t)(b * 2048 + tq)) * 1024u + h * 64 + qq * 16;
#pragma unroll
        for (int j4 = 0; j4 < 4; ++j4) {
            float4 a = *(float4*)(oa + j4 * 4);
            a.x = wm::__float_to_tf32(a.x * inv);
            a.y = wm::__float_to_tf32(a.y * inv);
            a.z = wm::__float_to_tf32(a.z * inv);
            a.w = wm::__float_to_tf32(a.w * inv);
            *(float4*)(dst + j4 * 4) = a;
        }
    }
}

// ---------------------------------------------------------------------------
// Launch
// ---------------------------------------------------------------------------
extern "C" void kernel_launch(void* const* d_in, const int* in_sizes, int n_in,
                              void* d_out, int out_size)
{
    const float* x     = (const float*)d_in[0];
    const float* Wqkv  = (const float*)d_in[1];
    const float* bqkv  = (const float*)d_in[2];
    const float* Wproj = (const float*)d_in[3];
    const float* bproj = (const float*)d_in[4];
    float* out = (float*)d_out;

    float *q, *k, *v, *yt, *xr, *wqkvr, *wprojr;
    cudaGetSymbolAddress((void**)&q,  g_q);
    cudaGetSymbolAddress((void**)&k,  g_k);
    cudaGetSymbolAddress((void**)&v,  g_v);
    cudaGetSymbolAddress((void**)&yt, g_yt);
    cudaGetSymbolAddress((void**)&xr, g_xr);
    cudaGetSymbolAddress((void**)&wqkvr, g_wqkvr);
    cudaGetSymbolAddress((void**)&wprojr, g_wprojr);

    const int M = 4096, C = 1024;

    // 0) tf32 pre-round passes
    {
        int n4 = (M * C) / 4;
        round_tf32_kernel<<<(n4 + 255) / 256, 256>>>(x, xr, n4);
        n4 = (C * 3 * C) / 4;
        round_tf32_kernel<<<(n4 + 255) / 256, 256>>>(Wqkv, wqkvr, n4);
        n4 = (C * C) / 4;
        round_tf32_kernel<<<(n4 + 255) / 256, 256>>>(Wproj, wprojr, n4);
    }

    const int gemm_smem = (G_STG * (G_ASZ + G_BSZ) + 16 * G_BLD) * (int)sizeof(float);
    cudaFuncSetAttribute(gemm_tf32_kernel,
                         cudaFuncAttributeMaxDynamicSharedMemorySize, gemm_smem);

    // 1) QKV projection (tf32-rounded outputs)
    {
        dim3 grid(3 * C / 128, M / 128);   // (24, 32)
        gemm_tf32_kernel<<<grid, 256, gemm_smem>>>(xr, wqkvr, bqkv, q, k, v,
                                                   M, 3 * C, C, 1);
    }

    // 2) Flash attention (causal) -> yt (tf32-rounded)
    {
        const int smem = (3 * 128 * FLD + 4 * 64 * FLD) * (int)sizeof(float); // 184320
        cudaFuncSetAttribute(flash_tf32_kernel,
                             cudaFuncAttributeMaxDynamicSharedMemorySize, smem);
        dim3 grid(2048 / 128, 32);         // (16, 32)
        flash_tf32_kernel<<<grid, 512, smem>>>(q, k, v, yt);
    }

    // 3) Output projection (fp32 output)
    {
        dim3 grid(C / 128, M / 128);       // (8, 32)
        gemm_tf32_kernel<<<grid, 256, gemm_smem>>>(yt, wprojr, bproj,
                                                   out, out, out, M, C, C, 0);
    }
}

// round 8
// speedup vs baseline: 3.6315x; 2.8848x over previous
#include <cuda_runtime.h>
#include <cuda_fp16.h>
#include <mma.h>
#include <cstdint>

namespace wm = nvcuda::wmma;

// ---------------------------------------------------------------------------
// Scratch (device globals)
// ---------------------------------------------------------------------------
__device__ __half g_q [2u * 2048u * 1024u];
__device__ __half g_k [2u * 2048u * 1024u];
__device__ __half g_v [2u * 2048u * 1024u];
__device__ __half g_yt[2u * 2048u * 1024u];
__device__ __half g_xh   [4096u * 1024u];
__device__ __half g_wqkvh[1024u * 3072u];
__device__ __half g_wprojh[1024u * 1024u];

// ---------------------------------------------------------------------------
// cp.async helpers
// ---------------------------------------------------------------------------
__device__ __forceinline__ uint32_t smem_u32(const void* p) {
    return (uint32_t)__cvta_generic_to_shared(p);
}
__device__ __forceinline__ void cp16(uint32_t dst, const void* src) {
    asm volatile("cp.async.cg.shared.global [%0], [%1], 16;"
                 :: "r"(dst), "l"(src) : "memory");
}
__device__ __forceinline__ void cp_commit() {
    asm volatile("cp.async.commit_group;" ::: "memory");
}
template <int N>
__device__ __forceinline__ void cp_wait() {
    asm volatile("cp.async.wait_group %0;" :: "n"(N) : "memory");
}

// ---------------------------------------------------------------------------
// fp32 -> fp16 conversion pass (8 elements/thread)
// ---------------------------------------------------------------------------
__global__ void to_half_kernel(const float* __restrict__ in,
                               __half* __restrict__ out, int n8)
{
    int i = blockIdx.x * blockDim.x + threadIdx.x;
    if (i < n8) {
        float4 a = ((const float4*)in)[i * 2];
        float4 b = ((const float4*)in)[i * 2 + 1];
        __half h[8];
        h[0] = __float2half_rn(a.x); h[1] = __float2half_rn(a.y);
        h[2] = __float2half_rn(a.z); h[3] = __float2half_rn(a.w);
        h[4] = __float2half_rn(b.x); h[5] = __float2half_rn(b.y);
        h[6] = __float2half_rn(b.z); h[7] = __float2half_rn(b.w);
        ((uint4*)out)[i] = *(uint4*)h;
    }
}

// ---------------------------------------------------------------------------
// FP16 WMMA GEMM (fp32 accumulate), 3-stage cp.async, 2 CTAs/SM.
// C = A[M,K] @ B[K,N] + bias[N]. BM=BN=128, BK=32, 256 thr (8 warps 4x2).
// ROUND_OUT=1: outputs stored as half (via smem staging). 0: fp32 direct.
// ---------------------------------------------------------------------------
#define G_ALD 40        // halves
#define G_BLD 136       // halves
#define G_ASZ (128 * G_ALD)       // halves per A stage
#define G_BSZ (32 * G_BLD)        // halves per B stage
#define G_STG 3
#define G_SMEM_BYTES (G_STG * (G_ASZ + G_BSZ) * 2 + 16 * G_BLD * 4)  // 65536

template <int ROUND_OUT>
__global__ __launch_bounds__(256, 2) void gemm_fp16_kernel(
    const __half* __restrict__ A, const __half* __restrict__ B,
    const float* __restrict__ bias,
    void* __restrict__ out0v, void* __restrict__ out1v, void* __restrict__ out2v,
    int M, int N, int K)
{
    extern __shared__ char gsmc[];
    __half* gsm  = (__half*)gsmc;
    float*  Brep = (float*)(gsmc + G_STG * (G_ASZ + G_BSZ) * 2);

    const int tid  = threadIdx.x;
    const int wid  = tid >> 5;
    const int wmi  = wid & 3;
    const int wni  = wid >> 2;
    const int m0   = blockIdx.y * 128;
    const int n0   = blockIdx.x * 128;

    for (int i = tid; i < 16 * 128; i += 256) {
        int r = i >> 7, c = i & 127;
        Brep[r * G_BLD + c] = bias[n0 + c];
    }
    __syncthreads();

    wm::fragment<wm::accumulator, 16, 16, 16, float> acc[2][4];
#pragma unroll
    for (int mi = 0; mi < 2; ++mi)
#pragma unroll
        for (int ni = 0; ni < 4; ++ni)
            wm::load_matrix_sync(acc[mi][ni], Brep + wni * 64 + ni * 16, G_BLD,
                                 wm::mem_row_major);
    __syncthreads();   // Brep region may be overwritten by staging later

    const int iters = K >> 5;

    auto issue_stage = [&](int stage) {
        const int s = stage % G_STG;
        const int k0 = stage << 5;
        __half* as = gsm + s * G_ASZ;
        __half* bs = gsm + G_STG * G_ASZ + s * G_BSZ;
        // A: 128 rows x 32 halves = 4 chunks/row, 512 chunks
#pragma unroll
        for (int t = 0; t < 2; ++t) {
            int f = tid + t * 256;
            int r = f >> 2, c8 = (f & 3) << 3;
            cp16(smem_u32(as + r * G_ALD + c8),
                 A + (size_t)(m0 + r) * K + k0 + c8);
        }
        // B: 32 rows x 128 halves = 16 chunks/row, 512 chunks
#pragma unroll
        for (int t = 0; t < 2; ++t) {
            int f = tid + t * 256;
            int r = f >> 4, c8 = (f & 15) << 3;
            cp16(smem_u32(bs + r * G_BLD + c8),
                 B + (size_t)(k0 + r) * N + n0 + c8);
        }
        cp_commit();
    };

    issue_stage(0);
    issue_stage(1);

    for (int it = 0; it < iters; ++it) {
        cp_wait<1>();
        __syncthreads();

        if (it + 2 < iters) issue_stage(it + 2);
        else                cp_commit();

        const int s = it % G_STG;
        const __half* as = gsm + s * G_ASZ;
        const __half* bs = gsm + G_STG * G_ASZ + s * G_BSZ;
#pragma unroll
        for (int ks = 0; ks < 2; ++ks) {
            wm::fragment<wm::matrix_a, 16, 16, 16, __half, wm::row_major> af[2];
            wm::fragment<wm::matrix_b, 16, 16, 16, __half, wm::row_major> bf[4];
#pragma unroll
            for (int mi = 0; mi < 2; ++mi)
                wm::load_matrix_sync(af[mi], as + (wmi * 32 + mi * 16) * G_ALD + ks * 16, G_ALD);
#pragma unroll
            for (int ni = 0; ni < 4; ++ni)
                wm::load_matrix_sync(bf[ni], bs + (ks * 16) * G_BLD + wni * 64 + ni * 16, G_BLD);
#pragma unroll
            for (int mi = 0; mi < 2; ++mi)
#pragma unroll
                for (int ni = 0; ni < 4; ++ni)
                    wm::mma_sync(acc[mi][ni], af[mi], bf[ni], acc[mi][ni]);
        }
        __syncthreads();
    }

    const int nc = n0 & 1023;
    if (ROUND_OUT) {
        // half output via smem staging (64 rows x 136 fp32 per pass)
        __half* outp = (n0 < 1024) ? (__half*)out0v
                     : ((n0 < 2048) ? (__half*)out1v : (__half*)out2v);
        float* stg = (float*)gsmc;
#pragma unroll
        for (int mi = 0; mi < 2; ++mi) {
            __syncthreads();
#pragma unroll
            for (int ni = 0; ni < 4; ++ni)
                wm::store_matrix_sync(stg + (wmi * 16) * G_BLD + wni * 64 + ni * 16,
                                      acc[mi][ni], G_BLD, wm::mem_row_major);
            __syncthreads();
#pragma unroll
            for (int t = 0; t < 4; ++t) {
                int idx = tid + t * 256;           // 1024 chunks of 8
                int sr = idx >> 4;
                int c8 = (idx & 15) << 3;
                int grow = m0 + (sr >> 4) * 32 + mi * 16 + (sr & 15);
                const float* s = stg + sr * G_BLD + c8;
                __half h[8];
#pragma unroll
                for (int j = 0; j < 8; ++j) h[j] = __float2half_rn(s[j]);
                *(uint4*)(outp + (size_t)grow * 1024 + nc + c8) = *(uint4*)h;
            }
        }
    } else {
        float* outp = (n0 < 1024) ? (float*)out0v
                    : ((n0 < 2048) ? (float*)out1v : (float*)out2v);
#pragma unroll
        for (int mi = 0; mi < 2; ++mi)
#pragma unroll
            for (int ni = 0; ni < 4; ++ni) {
                float* p = outp + (size_t)(m0 + wmi * 32 + mi * 16) * 1024
                                + nc + wni * 64 + ni * 16;
                wm::store_matrix_sync(p, acc[mi][ni], 1024, wm::mem_row_major);
            }
    }
}

// ---------------------------------------------------------------------------
// Flash attention (causal), FP16 WMMA. Br=128, Bc=64, hd=64, 512 threads.
// K/V double-buffered via cp.async. S and O accumulate fp32 in smem.
// ---------------------------------------------------------------------------
#define FLD 72

__global__ __launch_bounds__(512) void flash_fp16_kernel(
    const __half* __restrict__ Qg, const __half* __restrict__ Kg,
    const __half* __restrict__ Vg, __half* __restrict__ yt)
{
    extern __shared__ char smc[];
    __half* Qs  = (__half*)smc;                                   // [128][FLD]
    __half* Ps  = (__half*)(smc + 18432);                         // [128][FLD]
    float*  Ss  = (float*)(smc + 36864);                          // [128][FLD]
    float*  Oacc= (float*)(smc + 73728);                          // [128][FLD]
    __half* Ks0 = (__half*)(smc + 110592);                        // [64][FLD]
    __half* Ks1 = (__half*)(smc + 119808);
    __half* Vs0 = (__half*)(smc + 129024);
    __half* Vs1 = (__half*)(smc + 138240);
    __half* KsA[2] = { Ks0, Ks1 };
    __half* VsA[2] = { Vs0, Vs1 };

    const int qt  = gridDim.x - 1 - blockIdx.x;   // longest-first
    const int bh  = blockIdx.y;
    const int tid = threadIdx.x;
    const int wid = tid >> 5;
    const int wmi = wid & 3;
    const int wni = wid >> 2;

    const int r   = tid >> 2;        // softmax row (0..127)
    const int qq  = tid & 3;         // 16-col quarter

    const size_t head_off = (size_t)bh * 131072u;
    const __half* qb = Qg + head_off + (size_t)qt * 8192u;

    auto issue_kv = [&](int kt, int buf) {
        const __half* kb = Kg + head_off + (size_t)kt * 4096u;
        const __half* vb = Vg + head_off + (size_t)kt * 4096u;
        // 64 rows x 64 halves = 8 chunks/row -> 512 chunks each
        int rr = tid >> 3, c8 = (tid & 7) << 3;
        cp16(smem_u32(KsA[buf] + rr * FLD + c8), kb + rr * 64 + c8);
        cp16(smem_u32(VsA[buf] + rr * FLD + c8), vb + rr * 64 + c8);
        cp_commit();
    };

    issue_kv(0, 0);

    // Load Q (scaled by 0.125 — exact in fp16) + zero Oacc
    const __half2 sc = __half2half2(__float2half_rn(0.125f));
#pragma unroll
    for (int t = 0; t < 2; ++t) {
        int f = tid + t * 512;          // 1024 chunks of 8 halves
        int rr = f >> 3, c8 = (f & 7) << 3;
        uint4 raw = *(const uint4*)(qb + rr * 64 + c8);
        __half2* hp = (__half2*)&raw;
#pragma unroll
        for (int j = 0; j < 4; ++j) hp[j] = __hmul2(hp[j], sc);
        *(uint4*)(Qs + rr * FLD + c8) = raw;
    }
    for (int f = tid; f < 128 * FLD / 4; f += 512) {
        float4 z = {0.f, 0.f, 0.f, 0.f};
        *(float4*)(Oacc + f * 4) = z;
    }

    float mrow = -1e30f, lrow = 0.0f;
    int buf = 0;
    const int n_kt = 2 * (qt + 1);

    for (int kt = 0; kt < n_kt; ++kt) {
        cp_wait<0>();
        __syncthreads();

        if (kt + 1 < n_kt) issue_kv(kt + 1, buf ^ 1);

        // ---- S = Q @ K^T : warp tile 32x16, 4 k-steps ----
        {
            wm::fragment<wm::accumulator, 16, 16, 16, float> sacc[2];
#pragma unroll
            for (int mi = 0; mi < 2; ++mi) wm::fill_fragment(sacc[mi], 0.0f);
#pragma unroll
            for (int ks = 0; ks < 4; ++ks) {
                wm::fragment<wm::matrix_a, 16, 16, 16, __half, wm::row_major> af[2];
                wm::fragment<wm::matrix_b, 16, 16, 16, __half, wm::col_major> bf;
#pragma unroll
                for (int mi = 0; mi < 2; ++mi)
                    wm::load_matrix_sync(af[mi], Qs + (wmi * 32 + mi * 16) * FLD + ks * 16, FLD);
                wm::load_matrix_sync(bf, KsA[buf] + (wni * 16) * FLD + ks * 16, FLD);
#pragma unroll
                for (int mi = 0; mi < 2; ++mi)
                    wm::mma_sync(sacc[mi], af[mi], bf, sacc[mi]);
            }
#pragma unroll
            for (int mi = 0; mi < 2; ++mi)
                wm::store_matrix_sync(Ss + (wmi * 32 + mi * 16) * FLD + wni * 16,
                                      sacc[mi], FLD, wm::mem_row_major);
        }
        __syncthreads();

        // ---- Online softmax + in-place O rescale ----
        {
            float s[16];
            const float* srow = Ss + r * FLD + qq * 16;
            const bool need_mask = (kt >= 2 * qt);
#pragma unroll
            for (int j = 0; j < 16; ++j) s[j] = srow[j];
            if (need_mask) {
                const int row_g = qt * 128 + r;
                const int col_g0 = kt * 64 + qq * 16;
#pragma unroll
                for (int j = 0; j < 16; ++j)
                    if (col_g0 + j > row_g) s[j] = -1e30f;
            }
            float mx = -1e30f;
#pragma unroll
            for (int j = 0; j < 16; ++j) mx = fmaxf(mx, s[j]);
            mx = fmaxf(mx, __shfl_xor_sync(0xffffffffu, mx, 1));
            mx = fmaxf(mx, __shfl_xor_sync(0xffffffffu, mx, 2));

            float mn = fmaxf(mrow, mx);
            float alpha = __expf(mrow - mn);
            mrow = mn;

            float sum = 0.0f;
            __half ph[16];
#pragma unroll
            for (int j = 0; j < 16; ++j) {
                float p = __expf(s[j] - mn);
                sum += p;
                ph[j] = __float2half_rn(p);
            }
            __half* prow = Ps + r * FLD + qq * 16;
            *(uint4*)(prow)     = *(uint4*)(ph);
            *(uint4*)(prow + 8) = *(uint4*)(ph + 8);

            sum += __shfl_xor_sync(0xffffffffu, sum, 1);
            sum += __shfl_xor_sync(0xffffffffu, sum, 2);
            lrow = lrow * alpha + sum;

            float* oa = Oacc + r * FLD + qq * 16;
#pragma unroll
            for (int j4 = 0; j4 < 4; ++j4) {
                float4 a = *(float4*)(oa + j4 * 4);
                a.x *= alpha; a.y *= alpha; a.z *= alpha; a.w *= alpha;
                *(float4*)(oa + j4 * 4) = a;
            }
        }
        __syncthreads();

        // ---- Oacc += P @ V : 4 k-steps ----
        {
            wm::fragment<wm::accumulator, 16, 16, 16, float> oacc[2];
#pragma unroll
            for (int mi = 0; mi < 2; ++mi)
                wm::load_matrix_sync(oacc[mi],
                    Oacc + (wmi * 32 + mi * 16) * FLD + wni * 16, FLD, wm::mem_row_major);
#pragma unroll
            for (int ks = 0; ks < 4; ++ks) {
                wm::fragment<wm::matrix_a, 16, 16, 16, __half, wm::row_major> af[2];
                wm::fragment<wm::matrix_b, 16, 16, 16, __half, wm::row_major> bf;
#pragma unroll
                for (int mi = 0; mi < 2; ++mi)
                    wm::load_matrix_sync(af[mi], Ps + (wmi * 32 + mi * 16) * FLD + ks * 16, FLD);
                wm::load_matrix_sync(bf, VsA[buf] + (ks * 16) * FLD + wni * 16, FLD);
#pragma unroll
                for (int mi = 0; mi < 2; ++mi)
                    wm::mma_sync(oacc[mi], af[mi], bf, oacc[mi]);
            }
#pragma unroll
            for (int mi = 0; mi < 2; ++mi)
                wm::store_matrix_sync(Oacc + (wmi * 32 + mi * 16) * FLD + wni * 16,
                                      oacc[mi], FLD, wm::mem_row_major);
        }
        __syncthreads();
        buf ^= 1;
    }

    // ---- Epilogue: normalize, write half to [B,T,H,hd] ----
    {
        const int b = bh >> 4;
        const int h = bh & 15;
        const float inv = 1.0f / lrow;
        const int tq = qt * 128 + r;
        const float* oa = Oacc + r * FLD + qq * 16;
        __half* dst = yt + ((size_t)(b * 2048 + tq)) * 1024u + h * 64 + qq * 16;
        __half hh[16];
#pragma unroll
        for (int j = 0; j < 16; ++j) hh[j] = __float2half_rn(oa[j] * inv);
        *(uint4*)(dst)     = *(uint4*)(hh);
        *(uint4*)(dst + 8) = *(uint4*)(hh + 8);
    }
}

// ---------------------------------------------------------------------------
// Launch
// ---------------------------------------------------------------------------
extern "C" void kernel_launch(void* const* d_in, const int* in_sizes, int n_in,
                              void* d_out, int out_size)
{
    const float* x     = (const float*)d_in[0];
    const float* Wqkv  = (const float*)d_in[1];
    const float* bqkv  = (const float*)d_in[2];
    const float* Wproj = (const float*)d_in[3];
    const float* bproj = (const float*)d_in[4];
    float* out = (float*)d_out;

    __half *q, *k, *v, *yt, *xh, *wqkvh, *wprojh;
    cudaGetSymbolAddress((void**)&q,  g_q);
    cudaGetSymbolAddress((void**)&k,  g_k);
    cudaGetSymbolAddress((void**)&v,  g_v);
    cudaGetSymbolAddress((void**)&yt, g_yt);
    cudaGetSymbolAddress((void**)&xh, g_xh);
    cudaGetSymbolAddress((void**)&wqkvh, g_wqkvh);
    cudaGetSymbolAddress((void**)&wprojh, g_wprojh);

    const int M = 4096, C = 1024;

    // 0) fp32 -> fp16 conversion passes
    {
        int n8 = (M * C) / 8;
        to_half_kernel<<<(n8 + 255) / 256, 256>>>(x, xh, n8);
        n8 = (C * 3 * C) / 8;
        to_half_kernel<<<(n8 + 255) / 256, 256>>>(Wqkv, wqkvh, n8);
        n8 = (C * C) / 8;
        to_half_kernel<<<(n8 + 255) / 256, 256>>>(Wproj, wprojh, n8);
    }

    cudaFuncSetAttribute(gemm_fp16_kernel<1>,
                         cudaFuncAttributeMaxDynamicSharedMemorySize, G_SMEM_BYTES);
    cudaFuncSetAttribute(gemm_fp16_kernel<0>,
                         cudaFuncAttributeMaxDynamicSharedMemorySize, G_SMEM_BYTES);

    // 1) QKV projection -> half q/k/v
    {
        dim3 grid(3 * C / 128, M / 128);   // (24, 32)
        gemm_fp16_kernel<1><<<grid, 256, G_SMEM_BYTES>>>(xh, wqkvh, bqkv,
                                                         q, k, v, M, 3 * C, C);
    }

    // 2) Flash attention (causal) -> yt (half)
    {
        const int smem = 147456;
        cudaFuncSetAttribute(flash_fp16_kernel,
                             cudaFuncAttributeMaxDynamicSharedMemorySize, smem);
        dim3 grid(2048 / 128, 32);         // (16, 32)
        flash_fp16_kernel<<<grid, 512, smem>>>(q, k, v, yt);
    }

    // 3) Output projection -> fp32 out
    {
        dim3 grid(C / 128, M / 128);       // (8, 32)
        gemm_fp16_kernel<0><<<grid, 256, G_SMEM_BYTES>>>(yt, wprojh, bproj,
                                                         out, out, out, M, C, C);
    }
}